// round 5
// baseline (speedup 1.0000x reference)
#include <cuda_runtime.h>
#include <cuda_bf16.h>
#include <math.h>

// Problem dims
#define D        1024
#define S        32768
#define VOCAB    50257
#define CDIM     2048

// Attention: 296 role-blocks (2/SM) * 8 warps, 1 row per warp-iteration
#define ATT_BLOCKS 296
#define ATT_WARPS  8
#define NWARPS     (ATT_BLOCKS * ATT_WARPS)   // 2368

// K4a: 16 vocab rows per role-block (8 warps x 2 rows)
#define K4A_BLOCKS ((VOCAB + 15) / 16)        // 3142
#define FUSED_BLOCKS (ATT_BLOCKS + K4A_BLOCKS)

// Scratch (device globals; no allocation allowed)
// partial layout per block: [0]=m, [1]=z, [4..1027]=acc (16B aligned: stride 1028 floats)
__device__ float g_part[ATT_BLOCKS * 1028];
__device__ float g_concat[CDIM];          // [0..1023]=x (relu hidden), [1024..2047]=attn
__device__ float g_logits[VOCAB];
__device__ float g_stats[2];              // M, 1/Z for final softmax

__device__ __forceinline__ float warp_reduce_sum(float v) {
#pragma unroll
    for (int o = 16; o > 0; o >>= 1) v += __shfl_xor_sync(0xffffffffu, v, o);
    return v;
}

// ---------------------------------------------------------------------------
// K1: x = relu(W_h @ input + b_h); one warp per output row. Writes g_concat[0..D)
// ---------------------------------------------------------------------------
__global__ void k1_hidden(const float* __restrict__ inp,
                          const float* __restrict__ Wh,
                          const float* __restrict__ bh) {
    int warp = threadIdx.x >> 5, lane = threadIdx.x & 31;
    int row  = blockIdx.x * 8 + warp;      // 128 blocks * 8 warps = 1024 rows
    const float4* w4  = (const float4*)(Wh + (size_t)row * D);
    const float4* in4 = (const float4*)inp;
    float acc = 0.f;
#pragma unroll
    for (int k = 0; k < 8; k++) {
        float4 a = w4[k * 32 + lane];
        float4 b = in4[k * 32 + lane];
        acc += a.x * b.x + a.y * b.y + a.z * b.z + a.w * b.w;
    }
    acc = warp_reduce_sum(acc);
    if (lane == 0) g_concat[row] = fmaxf(acc + bh[row], 0.f);
}

// ---------------------------------------------------------------------------
// FUSED PHASE 1: blocks [0,296) = flash attention over encoder (134 MB,
// latency-bound); blocks [296,3438) = x-half of the vocab GEMV (206 MB,
// bandwidth-bound). Co-residency (3 CTAs/SM via launch_bounds) lets the
// streaming blocks consume the DRAM bandwidth the attention warps leave idle.
// Attention rows are processed in two passes (dot, then L1-hit reload for the
// accumulate) to keep live registers under the 85-reg cap without spills.
// ---------------------------------------------------------------------------
__global__ void __launch_bounds__(256, 3) fused_phase1(
        const float* __restrict__ enc,
        const float* __restrict__ Wo,
        const float* __restrict__ bo) {
    __shared__ __align__(16) float smem[1024 + ATT_WARPS * 1024 + 16]; // 36.1 KB

    int tid = threadIdx.x, warp = tid >> 5, lane = tid & 31;

    if (blockIdx.x < ATT_BLOCKS) {
        // ================= attention role =================
        float*  sq    = smem;                       // 1024 floats (q)
        float*  swacc = smem + 1024;                // 8*1024
        float*  sm_   = smem + 1024 + ATT_WARPS * 1024;
        float*  sz_   = sm_ + ATT_WARPS;
        float4* sq4   = (float4*)sq;

        for (int i = tid; i < D / 4; i += 256)
            sq4[i] = ((const float4*)g_concat)[i];
        __syncthreads();

        int gw = blockIdx.x * ATT_WARPS + warp;

        float  m = -INFINITY, z = 0.f;
        float4 acc[8];
#pragma unroll
        for (int k = 0; k < 8; k++) acc[k] = make_float4(0.f, 0.f, 0.f, 0.f);

        for (int r = gw; r < S; r += NWARPS) {
            const float4* e4 = (const float4*)(enc + (size_t)r * D);
            // pass 1: dot (row data not kept live across the reduce)
            float p = 0.f;
#pragma unroll
            for (int k = 0; k < 8; k++) {
                float4 a = e4[k * 32 + lane];
                float4 q = sq4[k * 32 + lane];
                p += a.x * q.x + a.y * q.y + a.z * q.z + a.w * q.w;
            }
            p = warp_reduce_sum(p);

            float nm = fmaxf(m, p);
            float sc = __expf(m - nm);
            float w  = __expf(p - nm);
            // pass 2: reload row (L1 hit) and accumulate
#pragma unroll
            for (int k = 0; k < 8; k++) {
                float4 a = e4[k * 32 + lane];
                acc[k].x = acc[k].x * sc + w * a.x;
                acc[k].y = acc[k].y * sc + w * a.y;
                acc[k].z = acc[k].z * sc + w * a.z;
                acc[k].w = acc[k].w * sc + w * a.w;
            }
            z = z * sc + w;
            m = nm;
        }

        if (lane == 0) sm_[warp] = m;
        __syncthreads();

        float mb = sm_[0];
#pragma unroll
        for (int wv = 1; wv < ATT_WARPS; wv++) mb = fmaxf(mb, sm_[wv]);

        float f = __expf(m - mb);
        if (lane == 0) sz_[warp] = z * f;
#pragma unroll
        for (int k = 0; k < 8; k++) {
            float4 s = make_float4(acc[k].x * f, acc[k].y * f, acc[k].z * f, acc[k].w * f);
            ((float4*)swacc)[warp * (D / 4) + k * 32 + lane] = s;
        }
        __syncthreads();

        // reduce 8 warp partials; thread tid handles one float4 column
        float* outp = &g_part[blockIdx.x * 1028];
        float4 s = make_float4(0.f, 0.f, 0.f, 0.f);
#pragma unroll
        for (int wv = 0; wv < ATT_WARPS; wv++) {
            float4 v = ((float4*)swacc)[wv * (D / 4) + tid];
            s.x += v.x; s.y += v.y; s.z += v.z; s.w += v.w;
        }
        ((float4*)(outp + 4))[tid] = s;       // offset 4 floats = 16B aligned
        if (tid == 0) {
            float zz = 0.f;
#pragma unroll
            for (int wv = 0; wv < ATT_WARPS; wv++) zz += sz_[wv];
            outp[0] = mb;
            outp[1] = zz;
        }
    } else {
        // ================= vocab GEMV (x half) role =================
        float4* sx = (float4*)smem;               // x: 256 float4 = 4 KB
        for (int i = tid; i < D / 4; i += 256)
            sx[i] = ((const float4*)g_concat)[i];
        __syncthreads();

        int vb = blockIdx.x - ATT_BLOCKS;
        int v0 = vb * 16 + warp * 2;
        int v1 = v0 + 1;
        const float4* w0 = (const float4*)(Wo + (size_t)((v0 < VOCAB) ? v0 : 0) * CDIM);
        const float4* w1 = (const float4*)(Wo + (size_t)((v1 < VOCAB) ? v1 : 0) * CDIM);

        float p0 = 0.f, p1 = 0.f;
#pragma unroll
        for (int k = 0; k < 8; k++) {
            float4 a0 = w0[k * 32 + lane];
            float4 a1 = w1[k * 32 + lane];
            float4 q  = sx[k * 32 + lane];
            p0 += a0.x * q.x + a0.y * q.y + a0.z * q.z + a0.w * q.w;
            p1 += a1.x * q.x + a1.y * q.y + a1.z * q.z + a1.w * q.w;
        }
#pragma unroll
        for (int o = 16; o > 0; o >>= 1) {
            p0 += __shfl_xor_sync(0xffffffffu, p0, o);
            p1 += __shfl_xor_sync(0xffffffffu, p1, o);
        }
        if (lane == 0 && v0 < VOCAB) g_logits[v0] = p0 + bo[v0];
        if (lane == 0 && v1 < VOCAB) g_logits[v1] = p1 + bo[v1];
    }
}

// ---------------------------------------------------------------------------
// K3: combine ATT_BLOCKS partials -> attn vector; writes g_concat[D..2D)
// 32 blocks x 128 threads; 32 columns/block, 4 b-slices per column.
// ---------------------------------------------------------------------------
__global__ void k3_combine() {
    __shared__ float sf[ATT_BLOCKS];
    __shared__ float red[128];
    __shared__ float slice[128];
    int tid = threadIdx.x;

    float lm = -INFINITY;
    for (int b = tid; b < ATT_BLOCKS; b += 128) lm = fmaxf(lm, g_part[b * 1028]);
    red[tid] = lm; __syncthreads();
    for (int s = 64; s > 0; s >>= 1) {
        if (tid < s) red[tid] = fmaxf(red[tid], red[tid + s]);
        __syncthreads();
    }
    float M = red[0]; __syncthreads();

    float lz = 0.f;
    for (int b = tid; b < ATT_BLOCKS; b += 128) {
        float fb = __expf(g_part[b * 1028] - M);
        sf[b] = fb;
        lz += fb * g_part[b * 1028 + 1];
    }
    red[tid] = lz; __syncthreads();
    for (int s = 64; s > 0; s >>= 1) {
        if (tid < s) red[tid] += red[tid + s];
        __syncthreads();
    }
    float invZ = 1.0f / red[0];
    __syncthreads();

    int col = blockIdx.x * 32 + (tid & 31);
    int sl  = tid >> 5;                       // 0..3
    float v = 0.f;
    for (int b = sl; b < ATT_BLOCKS; b += 4)
        v += sf[b] * g_part[b * 1028 + 4 + col];
    slice[tid] = v;
    __syncthreads();
    if (sl == 0) {
        float t = slice[tid] + slice[tid + 32] + slice[tid + 64] + slice[tid + 96];
        g_concat[D + col] = t * invZ;
    }
}

// ---------------------------------------------------------------------------
// K4b: logits += W_out[:, 1024:2048] @ attn; one warp per vocab row (206 MB).
// Same memory shape as the proven R2 K4 (42 regs, 512 thr, streams ~6.4TB/s).
// ---------------------------------------------------------------------------
__global__ void k4b_logits(const float* __restrict__ Wo) {
    __shared__ float4 sa[D / 4];              // attn: 4 KB
    int tid = threadIdx.x, warp = tid >> 5, lane = tid & 31;
    for (int i = tid; i < D / 4; i += blockDim.x)
        sa[i] = ((const float4*)(g_concat + D))[i];
    __syncthreads();

    int v = blockIdx.x * 16 + warp;
    if (v >= VOCAB) return;
    const float4* w4 = (const float4*)(Wo + (size_t)v * CDIM + D);
    float p = 0.f;
#pragma unroll
    for (int k = 0; k < 8; k++) {
        float4 a = w4[k * 32 + lane];
        float4 q = sa[k * 32 + lane];
        p += a.x * q.x + a.y * q.y + a.z * q.z + a.w * q.w;
    }
    p = warp_reduce_sum(p);
    if (lane == 0) g_logits[v] += p;
}

// ---------------------------------------------------------------------------
// K5: one-pass online (max, sumexp) over logits — reads 201KB once from L2
// ---------------------------------------------------------------------------
__global__ void k5_stats() {
    __shared__ float rm[1024], rz[1024];
    int tid = threadIdx.x;
    float m = -INFINITY, z = 0.f;
    for (int i = tid; i < VOCAB; i += 1024) {
        float l  = g_logits[i];
        float nm = fmaxf(m, l);
        z = z * __expf(m - nm) + __expf(l - nm);
        m = nm;
    }
    rm[tid] = m; rz[tid] = z; __syncthreads();
    for (int s = 512; s > 0; s >>= 1) {
        if (tid < s) {
            float m2 = rm[tid + s], z2 = rz[tid + s];
            float nm = fmaxf(rm[tid], m2);
            rz[tid] = rz[tid] * __expf(rm[tid] - nm) + z2 * __expf(m2 - nm);
            rm[tid] = nm;
        }
        __syncthreads();
    }
    if (tid == 0) { g_stats[0] = rm[0]; g_stats[1] = 1.0f / rz[0]; }
}

// ---------------------------------------------------------------------------
// K6: write softmax probabilities
// ---------------------------------------------------------------------------
__global__ void k6_out(float* __restrict__ out) {
    int i = blockIdx.x * 256 + threadIdx.x;
    if (i < VOCAB) out[i] = __expf(g_logits[i] - g_stats[0]) * g_stats[1];
}

// ---------------------------------------------------------------------------
extern "C" void kernel_launch(void* const* d_in, const int* in_sizes, int n_in,
                              void* d_out, int out_size) {
    const float* inp = (const float*)d_in[0];   // [1,1,1024]
    const float* enc = (const float*)d_in[1];   // [32768,1024]
    const float* Wh  = (const float*)d_in[2];   // [1024,1024]
    const float* bh  = (const float*)d_in[3];   // [1024]
    const float* Wo  = (const float*)d_in[4];   // [50257,2048]
    const float* bo  = (const float*)d_in[5];   // [50257]
    float* out = (float*)d_out;                 // [1,50257]

    k1_hidden<<<D / 8, 256>>>(inp, Wh, bh);
    fused_phase1<<<FUSED_BLOCKS, 256>>>(enc, Wo, bo);
    k3_combine<<<D / 32, 128>>>();
    k4b_logits<<<(VOCAB + 15) / 16, 512>>>(Wo);
    k5_stats<<<1, 1024>>>();
    k6_out<<<(VOCAB + 255) / 256, 256>>>(out);
}